// round 11
// baseline (speedup 1.0000x reference)
#include <cuda_runtime.h>
#include <cuda_bf16.h>

// InvertiblePWL, persistent wide-CTA kernel, FULLY UNROLLED 4 iterations:
//   out = eps * A[idx] + B[idx]
//   idx via magic-number floor: clamp e to [-5.05, 5.0],
//     r1 = fma.rm(e, 9.9, 49.5); r2 = add.rm(r1, 12582912.0);
//     idx = float_bits(r2) - 1262485503   in [0, 100]
//   A[i] = exp(p[i]) + 0.001
//   B[i] = (b0 + pref_excl[i]) - points[max(i-1,0)] * A[i]
// 296 CTAs x 1024 thr = 303,104 threads; n4 = 1e6 float4s -> exactly 4
// grid-stride steps, steps 0-2 unconditionally in bounds, step 3 predicated.

#define N_BINS 100
#define TPB    1024
#define GRID   296          // 2 CTAs/SM * 148 SMs

__device__ __forceinline__ float pwl_one(float e, const float2* __restrict__ sAB) {
    const float ec = fminf(fmaxf(e, -5.05f), 5.0f);
    const float r1 = __fmaf_rd(ec, 9.9f, 49.5f);
    const float r2 = __fadd_rd(r1, 12582912.0f);       // 1.5*2^23, ULP=1
    const int  idx = __float_as_int(r2) - 1262485503;  // floor(raw)+1 in [0,100]
    const float2 ab = sAB[idx];
    return fmaf(e, ab.x, ab.y);
}

__device__ __forceinline__ float4 pwl_vec(float4 e, const float2* __restrict__ sAB) {
    float4 r;
    r.x = pwl_one(e.x, sAB);
    r.y = pwl_one(e.y, sAB);
    r.z = pwl_one(e.z, sAB);
    r.w = pwl_one(e.w, sAB);
    return r;
}

__global__ void __launch_bounds__(TPB, 2)
pwl_kernel(const float4* __restrict__ eps,
           const float*  __restrict__ p,
           const float*  __restrict__ b,
           const float*  __restrict__ points,
           float4* __restrict__ out, int n4) {
    __shared__ float2 sAB[N_BINS + 1];

    const int t = threadIdx.x;

    // ---- Warp 0: build table. Lane l owns indices 4l..4l+3 (0..127).
    if (t < 32) {
        const float int_len = 10.0f / 99.0f;
        const int i0 = 4 * t;
        const float b0 = b[0];

        float pv[4], pts[4];
#pragma unroll
        for (int k = 0; k < 4; k++) {
            const int idx = i0 + k;
            pv[k]  = (idx <= N_BINS) ? p[idx] : 0.0f;
            const int s = (idx > 0) ? (idx - 1) : 0;
            pts[k] = (idx <= N_BINS) ? points[s] : 0.0f;
        }

        float a[4], d[4];
#pragma unroll
        for (int k = 0; k < 4; k++) {
            const int idx = i0 + k;
            a[k] = expf(pv[k]) + 0.001f;
            d[k] = (idx >= 1 && idx <= N_BINS - 1) ? int_len * a[k] : 0.0f;
        }

        float l1 = d[0] + d[1];
        float lsum = l1 + d[2] + d[3];

        float incl = lsum;
#pragma unroll
        for (int o = 1; o < 32; o <<= 1) {
            float u = __shfl_up_sync(0xFFFFFFFFu, incl, o);
            if (t >= o) incl += u;
        }
        const float lane_excl = incl - lsum;

        float ex[4];
        ex[0] = lane_excl;
        ex[1] = lane_excl + d[0];
        ex[2] = lane_excl + l1;
        ex[3] = lane_excl + l1 + d[2];

#pragma unroll
        for (int k = 0; k < 4; k++) {
            const int idx = i0 + k;
            if (idx <= N_BINS)
                sAB[idx] = make_float2(a[k], (b0 + ex[k]) - pts[k] * a[k]);
        }
    }

    const int S = GRID * TPB;                 // 303104
    const int i = blockIdx.x * TPB + t;       // i < S <= n4

    // Steps 0..2 are always in bounds (i + 2S <= 909,311 < 1e6).
    float4 e0 = eps[i];
    float4 e1 = eps[i + S];

    __syncthreads();                          // table visible; loads in flight

    float4 e2 = eps[i + 2 * S];
    out[i] = pwl_vec(e0, sAB);

    const bool last = (i + 3 * S) < n4;
    float4 e3;
    if (last) e3 = eps[i + 3 * S];
    out[i + S] = pwl_vec(e1, sAB);

    out[i + 2 * S] = pwl_vec(e2, sAB);

    if (last) out[i + 3 * S] = pwl_vec(e3, sAB);
}

extern "C" void kernel_launch(void* const* d_in, const int* in_sizes, int n_in,
                              void* d_out, int out_size) {
    const float* eps    = (const float*)d_in[0];   // [4000000]
    const float* p      = (const float*)d_in[1];   // [101]
    const float* b      = (const float*)d_in[2];   // [1]
    const float* points = (const float*)d_in[3];   // [100]
    float* out = (float*)d_out;

    const int n4 = out_size / 4;                   // 1,000,000
    pwl_kernel<<<GRID, TPB>>>((const float4*)eps, p, b, points,
                              (float4*)out, n4);
}

// round 12
// speedup vs baseline: 1.0332x; 1.0332x over previous
#include <cuda_runtime.h>
#include <cuda_bf16.h>

// InvertiblePWL, persistent wide-CTA kernel (best-measured config, R10):
//   out = eps * A[idx] + B[idx]
//   idx via magic-number floor: clamp e to [-5.05, 5.0],
//     r1 = fma.rm(e, 9.9, 49.5); r2 = add.rm(r1, 12582912.0);
//     idx = float_bits(r2) - 1262485503   in [0, 100]
//   A[i] = exp(p[i]) + 0.001
//   B[i] = (b0 + pref_excl[i]) - points[max(i-1,0)] * A[i]
// 296 CTAs x 1024 thr (2 CTAs/SM, 64 warps/SM), depth-2 rolling prefetch.
// Body batches the 4 LDS.64 gathers before the 4 FMAs so they pipeline.

#define N_BINS 100
#define TPB    1024
#define GRID   296          // 2 CTAs/SM * 148 SMs

__global__ void __launch_bounds__(TPB, 2)
pwl_kernel(const float4* __restrict__ eps,
           const float*  __restrict__ p,
           const float*  __restrict__ b,
           const float*  __restrict__ points,
           float4* __restrict__ out, int n4) {
    __shared__ float2 sAB[N_BINS + 1];

    const int t = threadIdx.x;

    // ---- Warp 0: build table. Lane l owns indices 4l..4l+3 (0..127).
    if (t < 32) {
        const float int_len = 10.0f / 99.0f;
        const int i0 = 4 * t;
        const float b0 = b[0];

        float pv[4], pts[4];
#pragma unroll
        for (int k = 0; k < 4; k++) {
            const int idx = i0 + k;
            pv[k]  = (idx <= N_BINS) ? p[idx] : 0.0f;
            const int s = (idx > 0) ? (idx - 1) : 0;
            pts[k] = (idx <= N_BINS) ? points[s] : 0.0f;
        }

        float a[4], d[4];
#pragma unroll
        for (int k = 0; k < 4; k++) {
            const int idx = i0 + k;
            a[k] = expf(pv[k]) + 0.001f;
            d[k] = (idx >= 1 && idx <= N_BINS - 1) ? int_len * a[k] : 0.0f;
        }

        float l1 = d[0] + d[1];
        float lsum = l1 + d[2] + d[3];

        float incl = lsum;
#pragma unroll
        for (int o = 1; o < 32; o <<= 1) {
            float u = __shfl_up_sync(0xFFFFFFFFu, incl, o);
            if (t >= o) incl += u;
        }
        const float lane_excl = incl - lsum;

        float ex[4];
        ex[0] = lane_excl;
        ex[1] = lane_excl + d[0];
        ex[2] = lane_excl + l1;
        ex[3] = lane_excl + l1 + d[2];

#pragma unroll
        for (int k = 0; k < 4; k++) {
            const int idx = i0 + k;
            if (idx <= N_BINS)
                sAB[idx] = make_float2(a[k], (b0 + ex[k]) - pts[k] * a[k]);
        }
    }

    // ---- Depth-2 prefetch before the barrier (hides table build).
    const int stride = GRID * TPB;
    int i0 = blockIdx.x * TPB + t;
    int i1 = i0 + stride;
    float4 cur, nxt;
    if (i0 < n4) cur = eps[i0];
    if (i1 < n4) nxt = eps[i1];

    __syncthreads();

    const float inv_len = 99.0f / 10.0f;

    // ---- Pipelined grid-stride loop: always two loads in flight.
    while (i0 < n4) {
        const int i2 = i1 + stride;
        float4 fut;
        if (i2 < n4) fut = eps[i2];

        // Batch the 4 index chains, then the 4 LDS.64 (they pipeline),
        // then the 4 FMAs.
        int ix[4];
        {
            const float ec = fminf(fmaxf(cur.x, -5.05f), 5.0f);
            ix[0] = __float_as_int(__fadd_rd(__fmaf_rd(ec, inv_len, 49.5f),
                                             12582912.0f)) - 1262485503;
        }
        {
            const float ec = fminf(fmaxf(cur.y, -5.05f), 5.0f);
            ix[1] = __float_as_int(__fadd_rd(__fmaf_rd(ec, inv_len, 49.5f),
                                             12582912.0f)) - 1262485503;
        }
        {
            const float ec = fminf(fmaxf(cur.z, -5.05f), 5.0f);
            ix[2] = __float_as_int(__fadd_rd(__fmaf_rd(ec, inv_len, 49.5f),
                                             12582912.0f)) - 1262485503;
        }
        {
            const float ec = fminf(fmaxf(cur.w, -5.05f), 5.0f);
            ix[3] = __float_as_int(__fadd_rd(__fmaf_rd(ec, inv_len, 49.5f),
                                             12582912.0f)) - 1262485503;
        }

        const float2 ab0 = sAB[ix[0]];
        const float2 ab1 = sAB[ix[1]];
        const float2 ab2 = sAB[ix[2]];
        const float2 ab3 = sAB[ix[3]];

        float4 r;
        r.x = fmaf(cur.x, ab0.x, ab0.y);
        r.y = fmaf(cur.y, ab1.x, ab1.y);
        r.z = fmaf(cur.z, ab2.x, ab2.y);
        r.w = fmaf(cur.w, ab3.x, ab3.y);
        out[i0] = r;

        cur = nxt;
        nxt = fut;
        i0 = i1;
        i1 = i2;
    }
}

extern "C" void kernel_launch(void* const* d_in, const int* in_sizes, int n_in,
                              void* d_out, int out_size) {
    const float* eps    = (const float*)d_in[0];   // [4000000]
    const float* p      = (const float*)d_in[1];   // [101]
    const float* b      = (const float*)d_in[2];   // [1]
    const float* points = (const float*)d_in[3];   // [100]
    float* out = (float*)d_out;

    const int n4 = out_size / 4;                   // 1,000,000
    pwl_kernel<<<GRID, TPB>>>((const float4*)eps, p, b, points,
                              (float4*)out, n4);
}